// round 5
// baseline (speedup 1.0000x reference)
#include <cuda_runtime.h>
#include <cuda_fp16.h>
#include <math.h>
#include <stdint.h>

#define N_NODES 8192
#define IN_F    512
#define OUT_F   64

// Scratch (device globals; no allocation allowed)
__device__ float  d_h[N_NODES * OUT_F];        // h = X @ W
__device__ float  d_r[N_NODES];                // r_j = h[j] . a_right
__device__ float  d_pmax[128];                 // per-CTA maxima of r (from k1)
__device__ __half d_HpT[80 * N_NODES];         // transposed [w*h | w | pad], n-major

// ---------------------------------------------------------------------------
// common helpers
// ---------------------------------------------------------------------------
__device__ __forceinline__ void mma16816(float* c,
    uint32_t a0, uint32_t a1, uint32_t a2, uint32_t a3,
    uint32_t b0, uint32_t b1) {
    asm volatile(
        "mma.sync.aligned.m16n8k16.row.col.f32.f16.f16.f32 "
        "{%0,%1,%2,%3},{%4,%5,%6,%7},{%8,%9},{%0,%1,%2,%3};\n"
        : "+f"(c[0]), "+f"(c[1]), "+f"(c[2]), "+f"(c[3])
        : "r"(a0), "r"(a1), "r"(a2), "r"(a3), "r"(b0), "r"(b1));
}

__device__ __forceinline__ void ldsm_x4(uint32_t& r0, uint32_t& r1,
                                        uint32_t& r2, uint32_t& r3, uint32_t addr) {
    asm volatile("ldmatrix.sync.aligned.m8n8.x4.shared.b16 {%0,%1,%2,%3}, [%4];\n"
        : "=r"(r0), "=r"(r1), "=r"(r2), "=r"(r3) : "r"(addr));
}
__device__ __forceinline__ void ldsm_x2(uint32_t& r0, uint32_t& r1, uint32_t addr) {
    asm volatile("ldmatrix.sync.aligned.m8n8.x2.shared.b16 {%0,%1}, [%2];\n"
        : "=r"(r0), "=r"(r1) : "r"(addr));
}

__device__ __forceinline__ void cpa16(void* dst, const void* src) {
    uint32_t d = (uint32_t)__cvta_generic_to_shared(dst);
    asm volatile("cp.async.cg.shared.global [%0], [%1], 16;\n" :: "r"(d), "l"(src));
}
#define CP_COMMIT() asm volatile("cp.async.commit_group;\n" ::: "memory")
#define CP_WAIT(n)  asm volatile("cp.async.wait_group %0;\n" :: "n"(n) : "memory")

__device__ __forceinline__ float elu1(float x) {
    return x > 0.f ? x : expm1f(x);
}

// ---------------------------------------------------------------------------
// K1: h = X @ W  via fp16 mma (8192x512 @ 512x64), fp32 accumulate.
// Fused: r_j = h[j].a_right and per-CTA max(r) -> d_pmax[128].
// ---------------------------------------------------------------------------
#define K1_XS   (3 * 64 * 68)                       // floats
#define K1_SMEM (K1_XS * 4 + 64 * 520 * 2)          // 118784 B

__global__ void __launch_bounds__(128)
k1_mma(const float* __restrict__ X, const float* __restrict__ W,
       const float* __restrict__ avec) {
    extern __shared__ char sm1[];
    float*  Xs = (float*)sm1;                        // [3][64][68]
    __half* Wt = (__half*)(sm1 + K1_XS * 4);         // [64 n][520 k]
    __shared__ float ar_s[64];
    __shared__ float wmax[4];

    const int tid  = threadIdx.x;
    const int warp = tid >> 5;
    const int lane = tid & 31;
    const int g    = lane >> 2;
    const int t    = lane & 3;
    const int row0 = blockIdx.x * 64;

    if (tid < 64) ar_s[tid] = avec[OUT_F + tid];

    for (int i = 0; i < 64; ++i) {
        int idx = i * 128 + tid;
        int k = idx >> 4, n = (idx & 15) * 4;
        float4 f = ((const float4*)W)[idx];
        Wt[(n + 0) * 520 + k] = __float2half(f.x);
        Wt[(n + 1) * 520 + k] = __float2half(f.y);
        Wt[(n + 2) * 520 + k] = __float2half(f.z);
        Wt[(n + 3) * 520 + k] = __float2half(f.w);
    }

    auto issueX = [&](int c) {
        int kc = c * 64;
        float* Xd = Xs + (c % 3) * 64 * 68;
#pragma unroll
        for (int q = 0; q < 8; ++q) {
            int idx = q * 128 + tid;
            int rr = idx >> 4, c4 = idx & 15;
            cpa16(Xd + rr * 68 + c4 * 4,
                  X + (size_t)(row0 + rr) * IN_F + kc + c4 * 4);
        }
    };
    issueX(0); CP_COMMIT();
    issueX(1); CP_COMMIT();

    float acc[8][4];
#pragma unroll
    for (int n = 0; n < 8; ++n)
#pragma unroll
        for (int i = 0; i < 4; ++i) acc[n][i] = 0.f;

    const int rb = warp * 16;
    for (int c = 0; c < 8; ++c) {
        CP_WAIT(1);
        __syncthreads();
        if (c + 2 < 8) issueX(c + 2);
        CP_COMMIT();

        const float* Xst = Xs + (c % 3) * 64 * 68;
#pragma unroll
        for (int ks = 0; ks < 4; ++ks) {
            int kk = ks * 16 + 2 * t;
            float2 f;
            __half2 h2;
            f = *(const float2*)&Xst[(rb + g) * 68 + kk];
            h2 = __float22half2_rn(f); uint32_t a0 = *(uint32_t*)&h2;
            f = *(const float2*)&Xst[(rb + g + 8) * 68 + kk];
            h2 = __float22half2_rn(f); uint32_t a1 = *(uint32_t*)&h2;
            f = *(const float2*)&Xst[(rb + g) * 68 + kk + 8];
            h2 = __float22half2_rn(f); uint32_t a2 = *(uint32_t*)&h2;
            f = *(const float2*)&Xst[(rb + g + 8) * 68 + kk + 8];
            h2 = __float22half2_rn(f); uint32_t a3 = *(uint32_t*)&h2;

            int kg = c * 64 + kk;
#pragma unroll
            for (int nt = 0; nt < 8; ++nt) {
                int n = nt * 8 + g;
                uint32_t b0 = *(const uint32_t*)&Wt[n * 520 + kg];
                uint32_t b1 = *(const uint32_t*)&Wt[n * 520 + kg + 8];
                mma16816(acc[nt], a0, a1, a2, a3, b0, b1);
            }
        }
    }

    const int rlo = row0 + rb + g;
    const int rhi = rlo + 8;
    float rlo_p = 0.f, rhi_p = 0.f;
#pragma unroll
    for (int nt = 0; nt < 8; ++nt) {
        int c0 = nt * 8 + 2 * t;
        *(float2*)&d_h[(size_t)rlo * OUT_F + c0] = make_float2(acc[nt][0], acc[nt][1]);
        *(float2*)&d_h[(size_t)rhi * OUT_F + c0] = make_float2(acc[nt][2], acc[nt][3]);
        rlo_p += acc[nt][0] * ar_s[c0] + acc[nt][1] * ar_s[c0 + 1];
        rhi_p += acc[nt][2] * ar_s[c0] + acc[nt][3] * ar_s[c0 + 1];
    }
    const unsigned full = 0xffffffffu;
    rlo_p += __shfl_xor_sync(full, rlo_p, 1);
    rlo_p += __shfl_xor_sync(full, rlo_p, 2);
    rhi_p += __shfl_xor_sync(full, rhi_p, 1);
    rhi_p += __shfl_xor_sync(full, rhi_p, 2);
    if (t == 0) {
        d_r[rlo] = rlo_p;
        d_r[rhi] = rhi_p;
    }
    float m = (t == 0) ? fmaxf(rlo_p, rhi_p) : -3.4e38f;
#pragma unroll
    for (int off = 16; off > 0; off >>= 1)
        m = fmaxf(m, __shfl_xor_sync(full, m, off));
    if (lane == 0) wmax[warp] = m;
    __syncthreads();
    if (tid == 0)
        d_pmax[blockIdx.x] = fmaxf(fmaxf(wmax[0], wmax[1]), fmaxf(wmax[2], wmax[3]));
}

// ---------------------------------------------------------------------------
// K3: w_j = exp(r_j - m); build HpT[c][j] (fp16, n-major):
//     c<64: w*h[j][c]; c==64: w; c in 65..71: 0. (only 72 rows used)
// ---------------------------------------------------------------------------
__global__ void k3_build() {
    __shared__ float hs[128][65];
    __shared__ float red[128];
    const int tid = threadIdx.x;
    const int j0  = blockIdx.x * 128;

    red[tid] = d_pmax[tid];
    __syncthreads();
    for (int st = 64; st > 0; st >>= 1) {
        if (tid < st) red[tid] = fmaxf(red[tid], red[tid + st]);
        __syncthreads();
    }
    const float smax = red[0];

#pragma unroll
    for (int it = 0; it < 64; ++it) {
        int idx = it * 128 + tid;
        int rr = idx >> 6, cc = idx & 63;
        hs[rr][cc] = d_h[(size_t)(j0 + rr) * OUT_F + cc];
    }
    __syncthreads();
    float w = expf(d_r[j0 + tid] - smax);
#pragma unroll
    for (int c = 0; c < 72; ++c) {
        float v = (c < 64) ? w * hs[tid][c] : ((c == 64) ? w : 0.f);
        d_HpT[(size_t)c * N_NODES + j0 + tid] = __float2half(v);
    }
}

// ---------------------------------------------------------------------------
// K4: C[8192 x 72] = A(0/1 int32) @ Hp(fp16), then out = elu(num/den)
// 128 CTAs x 512 threads (16 warps = rg 0..3 x ng 0..3).
// N-tiles (9 of them) split 3/2/2/2 across ng. 5-stage ring, prefetch 4.
// A: raw int32 cp.async -> smem convert -> fp16 double buffer; ldmatrix frags.
// ---------------------------------------------------------------------------
#define K4_STAGES 5
#define AI_STAGE (64 * 68)                 // ints per stage
#define AF_STAGE (64 * 72)                 // halves per stage
#define B_STAGE  (72 * 72)                 // halves per stage
#define OFF_AF   (K4_STAGES * AI_STAGE * 4)            // 87040
#define OFF_B    (OFF_AF + 2 * AF_STAGE * 2)           // 105472
#define OFF_DEN  (OFF_B + K4_STAGES * B_STAGE * 2)     // 157312
#define K4_SMEM  (OFF_DEN + 256)

__global__ void __launch_bounds__(512)
k4_main(const int* __restrict__ adj, float* __restrict__ out) {
    extern __shared__ char sm4[];
    int*    AIsm  = (int*)sm4;                          // [5][64][68] int32
    __half* Afp   = (__half*)(sm4 + OFF_AF);            // [2][64][72] fp16
    __half* Bsm   = (__half*)(sm4 + OFF_B);             // [5][72][72] fp16
    float*  den_s = (float*)(sm4 + OFF_DEN);

    const int tid  = threadIdx.x;
    const int warp = tid >> 5;
    const int lane = tid & 31;
    const int t    = lane & 3;
    const int rg   = warp >> 2;            // 0..3  (16 rows each)
    const int ng   = warp & 3;             // 0..3  (n-tile groups 3/2/2/2)
    const int row0 = blockIdx.x * 64;

    const int baseT = (ng == 0) ? 0 : (ng == 1 ? 3 : (ng == 2 ? 5 : 7));
    const int cntT  = (ng == 0) ? 3 : 2;

    const uint32_t A0 = (uint32_t)__cvta_generic_to_shared(Afp);
    const uint32_t B0 = (uint32_t)__cvta_generic_to_shared(Bsm);

    // ldmatrix lane addressing (verified in R3/R4)
    const int quad = lane >> 3;            // 0..3
    const int qr   = lane & 7;
    const int rb   = rg * 16;
    const uint32_t aoff = (uint32_t)((rb + (quad & 1) * 8 + qr) * (72 * 2)
                                     + (quad >> 1) * 16);
    // pair of tiles (baseT, baseT+1): 16 consecutive n-rows
    const uint32_t boffp = (uint32_t)((baseT * 8 + (quad >> 1) * 8 + qr) * (72 * 2)
                                      + (quad & 1) * 16);
    // single tile (baseT+2) for ng==0 (x2: lanes 0..15)
    const uint32_t boffs = (uint32_t)(((baseT + 2) * 8 + qr) * (72 * 2)
                                      + (quad & 1) * 16);

    // --- async producers: A int32 + B fp16 in one commit group per chunk ---
    auto issue = [&](int c) {
        int kc = c * 64;
        int st = c % K4_STAGES;
        int*    Ad = AIsm + st * AI_STAGE;
        __half* Bd = Bsm + st * B_STAGE;
#pragma unroll
        for (int q = 0; q < 2; ++q) {
            int idx = q * 512 + tid;           // 1024 int4 = 64 rows x 16
            int rr = idx >> 4, c4 = idx & 15;
            cpa16(Ad + rr * 68 + c4 * 4,
                  adj + (size_t)(row0 + rr) * N_NODES + kc + c4 * 4);
        }
        {
            int idx = tid;                     // 576 int4 = 72 rows x 8
            int rr = idx >> 3, s = idx & 7;
            cpa16(Bd + rr * 72 + s * 8,
                  d_HpT + (size_t)rr * N_NODES + kc + s * 8);
            if (tid < 64) {
                int idx2 = 512 + tid;
                int rr2 = idx2 >> 3, s2 = idx2 & 7;
                cpa16(Bd + rr2 * 72 + s2 * 8,
                      d_HpT + (size_t)rr2 * N_NODES + kc + s2 * 8);
            }
        }
    };

    // smem convert: int32 stage (c%5) -> fp16 buffer (c&1). Reads own-thread data.
    auto convA = [&](int c) {
        const int4* src = (const int4*)(AIsm + (c % K4_STAGES) * AI_STAGE);
        __half*     dst = Afp + (c & 1) * AF_STAGE;
#pragma unroll
        for (int q = 0; q < 2; ++q) {
            int idx = q * 512 + tid;
            int rr = idx >> 4, c4 = idx & 15;
            int4 v = src[rr * 17 + c4];
            uint32_t h01 = (v.x ? 0x3C00u : 0u) | (v.y ? 0x3C000000u : 0u);
            uint32_t h23 = (v.z ? 0x3C00u : 0u) | (v.w ? 0x3C000000u : 0u);
            *(uint2*)&dst[rr * 72 + c4 * 4] = make_uint2(h01, h23);
        }
    };

    issue(0); CP_COMMIT();
    issue(1); CP_COMMIT();
    issue(2); CP_COMMIT();
    issue(3); CP_COMMIT();

    float acc[3][4];
#pragma unroll
    for (int n = 0; n < 3; ++n)
#pragma unroll
        for (int i = 0; i < 4; ++i) acc[n][i] = 0.f;

    // prologue: chunk 0 landed (own-thread), convert it, make visible
    CP_WAIT(3);
    convA(0);
    __syncthreads();

    for (int c = 0; c < 128; ++c) {
        if (c + 4 < 128) issue(c + 4);
        CP_COMMIT();                      // always commit: stable group count
        CP_WAIT(3);                       // chunk c+1 landed (own-thread)

        if (c + 1 < 128) convA(c + 1);    // ILP-overlaps MMAs below

        const uint32_t Ab = A0 + (c & 1) * (AF_STAGE * 2) + aoff;
        const uint32_t Bb = B0 + (c % K4_STAGES) * (B_STAGE * 2);

#pragma unroll
        for (int ks = 0; ks < 4; ++ks) {
            uint32_t a0, a1, a2, a3;
            ldsm_x4(a0, a1, a2, a3, Ab + ks * 32);
            uint32_t b[6];
            ldsm_x4(b[0], b[1], b[2], b[3], Bb + boffp + ks * 32);
            if (ng == 0) ldsm_x2(b[4], b[5], Bb + boffs + ks * 32);
            mma16816(acc[0], a0, a1, a2, a3, b[0], b[1]);
            mma16816(acc[1], a0, a1, a2, a3, b[2], b[3]);
            if (ng == 0) mma16816(acc[2], a0, a1, a2, a3, b[4], b[5]);
        }

        __syncthreads();                  // conv(c+1), B(c+1) visible; stage reuse fence
    }

    // epilogue: den = col 64 = global tile 8 = (ng==3, local 1), t==0
    const int g   = lane >> 2;
    const int r0l = rb + g;
    if (ng == 3 && t == 0) {
        den_s[r0l]     = acc[1][0];
        den_s[r0l + 8] = acc[1][2];
    }
    __syncthreads();
    float inv_lo = 1.f / den_s[r0l];
    float inv_hi = 1.f / den_s[r0l + 8];

    const int rlo = row0 + r0l;
    const int rhi = rlo + 8;
#pragma unroll
    for (int nt = 0; nt < 3; ++nt) {
        if (nt >= cntT) break;
        int gt = baseT + nt;
        if (gt >= 8) break;               // tile 8 is den
        int c0 = gt * 8 + 2 * t;
        float2 vlo = make_float2(elu1(acc[nt][0] * inv_lo), elu1(acc[nt][1] * inv_lo));
        float2 vhi = make_float2(elu1(acc[nt][2] * inv_hi), elu1(acc[nt][3] * inv_hi));
        *(float2*)&out[(size_t)rlo * OUT_F + c0] = vlo;
        *(float2*)&out[(size_t)rhi * OUT_F + c0] = vhi;
    }
}

// ---------------------------------------------------------------------------
extern "C" void kernel_launch(void* const* d_in, const int* in_sizes, int n_in,
                              void* d_out, int out_size) {
    const float* X    = (const float*)d_in[0];   // node_features 8192x512
    const int*   adj  = (const int*)  d_in[1];   // adjacency 8192x8192
    const float* W    = (const float*)d_in[2];   // weight 512x64
    const float* avec = (const float*)d_in[3];   // attention vector 128x1
    float* out = (float*)d_out;                  // 8192x64

    cudaFuncSetAttribute(k1_mma, cudaFuncAttributeMaxDynamicSharedMemorySize, K1_SMEM);
    cudaFuncSetAttribute(k4_main, cudaFuncAttributeMaxDynamicSharedMemorySize, K4_SMEM);

    k1_mma<<<128, 128, K1_SMEM>>>(X, W, avec);
    k3_build<<<64, 128>>>();
    k4_main<<<128, 512, K4_SMEM>>>(adj, out);
}

// round 6
// speedup vs baseline: 1.2553x; 1.2553x over previous
#include <cuda_runtime.h>
#include <cuda_fp16.h>
#include <math.h>
#include <stdint.h>

#define N_NODES 8192
#define IN_F    512
#define OUT_F   64

__device__ float  d_h[N_NODES * OUT_F];
__device__ float  d_r[N_NODES];
__device__ float  d_pmax[128];
__device__ __half d_HpT[80 * N_NODES];
__device__ float  d_part[2 * N_NODES * 80];

__device__ __forceinline__ void mma16816(float* c,
    uint32_t a0, uint32_t a1, uint32_t a2, uint32_t a3,
    uint32_t b0, uint32_t b1) {
    asm volatile(
        "mma.sync.aligned.m16n8k16.row.col.f32.f16.f16.f32 "
        "{%0,%1,%2,%3},{%4,%5,%6,%7},{%8,%9},{%0,%1,%2,%3};\n"
        : "+f"(c[0]), "+f"(c[1]), "+f"(c[2]), "+f"(c[3])
        : "r"(a0), "r"(a1), "r"(a2), "r"(a3), "r"(b0), "r"(b1));
}

__device__ __forceinline__ void ldsm_x4(uint32_t& r0, uint32_t& r1,
                                        uint32_t& r2, uint32_t& r3, uint32_t addr) {
    asm volatile("ldmatrix.sync.aligned.m8n8.x4.shared.b16 {%0,%1,%2,%3}, [%4];\n"
        : "=r"(r0), "=r"(r1), "=r"(r2), "=r"(r3) : "r"(addr));
}
__device__ __forceinline__ void ldsm_x2(uint32_t& r0, uint32_t& r1, uint32_t addr) {
    asm volatile("ldmatrix.sync.aligned.m8n8.x2.shared.b16 {%0,%1}, [%2];\n"
        : "=r"(r0), "=r"(r1) : "r"(addr));
}

__device__ __forceinline__ void cpa16(void* dst, const void* src) {
    uint32_t d = (uint32_t)__cvta_generic_to_shared(dst);
    asm volatile("cp.async.cg.shared.global [%0], [%1], 16;\n" :: "r"(d), "l"(src));
}
#define CP_COMMIT() asm volatile("cp.async.commit_group;\n" ::: "memory")
#define CP_WAIT(n)  asm volatile("cp.async.wait_group %0;\n" :: "n"(n) : "memory")

__device__ __forceinline__ float elu1(float x) {
    return x > 0.f ? x : expm1f(x);
}

// ---------------------------------------------------------------------------
// K1: h = X @ W via fp16 mma; fused r = h.a_right, per-CTA max -> d_pmax.
// ---------------------------------------------------------------------------
#define K1_XS   (3 * 64 * 68)
#define K1_SMEM (K1_XS * 4 + 64 * 520 * 2)

__global__ void __launch_bounds__(128)
k1_mma(const float* __restrict__ X, const float* __restrict__ W,
       const float* __restrict__ avec) {
    extern __shared__ char sm1[];
    float*  Xs = (float*)sm1;
    __half* Wt = (__half*)(sm1 + K1_XS * 4);
    __shared__ float ar_s[64];
    __shared__ float wmax[4];

    const int tid  = threadIdx.x;
    const int warp = tid >> 5;
    const int lane = tid & 31;
    const int g    = lane >> 2;
    const int t    = lane & 3;
    const int row0 = blockIdx.x * 64;

    if (tid < 64) ar_s[tid] = avec[OUT_F + tid];

    for (int i = 0; i < 64; ++i) {
        int idx = i * 128 + tid;
        int k = idx >> 4, n = (idx & 15) * 4;
        float4 f = ((const float4*)W)[idx];
        Wt[(n + 0) * 520 + k] = __float2half(f.x);
        Wt[(n + 1) * 520 + k] = __float2half(f.y);
        Wt[(n + 2) * 520 + k] = __float2half(f.z);
        Wt[(n + 3) * 520 + k] = __float2half(f.w);
    }

    auto issueX = [&](int c) {
        int kc = c * 64;
        float* Xd = Xs + (c % 3) * 64 * 68;
#pragma unroll
        for (int q = 0; q < 8; ++q) {
            int idx = q * 128 + tid;
            int rr = idx >> 4, c4 = idx & 15;
            cpa16(Xd + rr * 68 + c4 * 4,
                  X + (size_t)(row0 + rr) * IN_F + kc + c4 * 4);
        }
    };
    issueX(0); CP_COMMIT();
    issueX(1); CP_COMMIT();

    float acc[8][4];
#pragma unroll
    for (int n = 0; n < 8; ++n)
#pragma unroll
        for (int i = 0; i < 4; ++i) acc[n][i] = 0.f;

    const int rb = warp * 16;
    for (int c = 0; c < 8; ++c) {
        CP_WAIT(1);
        __syncthreads();
        if (c + 2 < 8) issueX(c + 2);
        CP_COMMIT();

        const float* Xst = Xs + (c % 3) * 64 * 68;
#pragma unroll
        for (int ks = 0; ks < 4; ++ks) {
            int kk = ks * 16 + 2 * t;
            float2 f;
            __half2 h2;
            f = *(const float2*)&Xst[(rb + g) * 68 + kk];
            h2 = __float22half2_rn(f); uint32_t a0 = *(uint32_t*)&h2;
            f = *(const float2*)&Xst[(rb + g + 8) * 68 + kk];
            h2 = __float22half2_rn(f); uint32_t a1 = *(uint32_t*)&h2;
            f = *(const float2*)&Xst[(rb + g) * 68 + kk + 8];
            h2 = __float22half2_rn(f); uint32_t a2 = *(uint32_t*)&h2;
            f = *(const float2*)&Xst[(rb + g + 8) * 68 + kk + 8];
            h2 = __float22half2_rn(f); uint32_t a3 = *(uint32_t*)&h2;

            int kg = c * 64 + kk;
#pragma unroll
            for (int nt = 0; nt < 8; ++nt) {
                int n = nt * 8 + g;
                uint32_t b0 = *(const uint32_t*)&Wt[n * 520 + kg];
                uint32_t b1 = *(const uint32_t*)&Wt[n * 520 + kg + 8];
                mma16816(acc[nt], a0, a1, a2, a3, b0, b1);
            }
        }
    }

    const int rlo = row0 + rb + g;
    const int rhi = rlo + 8;
    float rlo_p = 0.f, rhi_p = 0.f;
#pragma unroll
    for (int nt = 0; nt < 8; ++nt) {
        int c0 = nt * 8 + 2 * t;
        *(float2*)&d_h[(size_t)rlo * OUT_F + c0] = make_float2(acc[nt][0], acc[nt][1]);
        *(float2*)&d_h[(size_t)rhi * OUT_F + c0] = make_float2(acc[nt][2], acc[nt][3]);
        rlo_p += acc[nt][0] * ar_s[c0] + acc[nt][1] * ar_s[c0 + 1];
        rhi_p += acc[nt][2] * ar_s[c0] + acc[nt][3] * ar_s[c0 + 1];
    }
    const unsigned full = 0xffffffffu;
    rlo_p += __shfl_xor_sync(full, rlo_p, 1);
    rlo_p += __shfl_xor_sync(full, rlo_p, 2);
    rhi_p += __shfl_xor_sync(full, rhi_p, 1);
    rhi_p += __shfl_xor_sync(full, rhi_p, 2);
    if (t == 0) {
        d_r[rlo] = rlo_p;
        d_r[rhi] = rhi_p;
    }
    float m = (t == 0) ? fmaxf(rlo_p, rhi_p) : -3.4e38f;
#pragma unroll
    for (int off = 16; off > 0; off >>= 1)
        m = fmaxf(m, __shfl_xor_sync(full, m, off));
    if (lane == 0) wmax[warp] = m;
    __syncthreads();
    if (tid == 0)
        d_pmax[blockIdx.x] = fmaxf(fmaxf(wmax[0], wmax[1]), fmaxf(wmax[2], wmax[3]));
}

// ---------------------------------------------------------------------------
// K3: w_j = exp(r_j - m); build HpT (fp16, n-major, 72 rows)
// ---------------------------------------------------------------------------
__global__ void k3_build() {
    __shared__ float hs[128][65];
    __shared__ float red[128];
    const int tid = threadIdx.x;
    const int j0  = blockIdx.x * 128;

    red[tid] = d_pmax[tid];
    __syncthreads();
    for (int st = 64; st > 0; st >>= 1) {
        if (tid < st) red[tid] = fmaxf(red[tid], red[tid + st]);
        __syncthreads();
    }
    const float smax = red[0];

#pragma unroll
    for (int it = 0; it < 64; ++it) {
        int idx = it * 128 + tid;
        int rr = idx >> 6, cc = idx & 63;
        hs[rr][cc] = d_h[(size_t)(j0 + rr) * OUT_F + cc];
    }
    __syncthreads();
    float w = expf(d_r[j0 + tid] - smax);
#pragma unroll
    for (int c = 0; c < 72; ++c) {
        float v = (c < 64) ? w * hs[tid][c] : ((c == 64) ? w : 0.f);
        d_HpT[(size_t)c * N_NODES + j0 + tid] = __float2half(v);
    }
}

// ---------------------------------------------------------------------------
// K4: K-split partial GEMM. 256 CTAs = (rowBlk 0..127) x (half 0..1).
// 256 threads (8 warps = rg 0..3 x ng 0..1; ng0 tiles 0-4, ng1 tiles 5-8).
// 3-stage ring (prefetch 2), smem ~99.4KB -> 2 CTAs/SM for cross-CTA overlap.
// ---------------------------------------------------------------------------
#define NST 3
#define AI_STAGE (64 * 68)
#define AF_STAGE (64 * 72)
#define B_STAGE  (72 * 72)
#define OFF_AF   (NST * AI_STAGE * 4)
#define OFF_B    (OFF_AF + 2 * AF_STAGE * 2)
#define K4_SMEM  (OFF_B + NST * B_STAGE * 2)

__global__ void __launch_bounds__(256, 2)
k4_split(const int* __restrict__ adj) {
    extern __shared__ char sm4[];
    int*    AIsm = (int*)sm4;
    __half* Afp  = (__half*)(sm4 + OFF_AF);
    __half* Bsm  = (__half*)(sm4 + OFF_B);

    const int tid  = threadIdx.x;
    const int warp = tid >> 5;
    const int lane = tid & 31;
    const int t    = lane & 3;
    const int rg   = warp >> 1;
    const int ng   = warp & 1;
    const int rowBlk = blockIdx.x >> 1;
    const int half   = blockIdx.x & 1;
    const int row0   = rowBlk * 64;
    const int kOff   = half * 4096;

    const int baseT = ng * 5;
    const int cntT  = ng ? 4 : 5;

    const uint32_t A0 = (uint32_t)__cvta_generic_to_shared(Afp);
    const uint32_t B0 = (uint32_t)__cvta_generic_to_shared(Bsm);

    const int quad = lane >> 3;
    const int qr   = lane & 7;
    const int rb   = rg * 16;
    const uint32_t aoff = (uint32_t)((rb + (quad & 1) * 8 + qr) * (72 * 2)
                                     + (quad >> 1) * 16);
    uint32_t boffp[2];
#pragma unroll
    for (int p = 0; p < 2; ++p) {
        int n0 = (baseT + 2 * p) * 8;
        boffp[p] = (uint32_t)((n0 + (quad >> 1) * 8 + qr) * (72 * 2)
                              + (quad & 1) * 16);
    }
    const uint32_t boffs = (uint32_t)(((baseT + 4) * 8 + qr) * (72 * 2)
                                      + (quad & 1) * 16);

    auto issue = [&](int c) {
        int kc = kOff + c * 64;
        int st = c % NST;
        int*    Ad = AIsm + st * AI_STAGE;
        __half* Bd = Bsm + st * B_STAGE;
#pragma unroll
        for (int q = 0; q < 4; ++q) {
            int idx = q * 256 + tid;
            int rr = idx >> 4, c4 = idx & 15;
            cpa16(Ad + rr * 68 + c4 * 4,
                  adj + (size_t)(row0 + rr) * N_NODES + kc + c4 * 4);
        }
#pragma unroll
        for (int q = 0; q < 3; ++q) {
            int idx = q * 256 + tid;
            if (idx < 576) {
                int rr = idx >> 3, s = idx & 7;
                cpa16(Bd + rr * 72 + s * 8,
                      d_HpT + (size_t)rr * N_NODES + kc + s * 8);
            }
        }
    };

    auto convA = [&](int c) {
        const int4* src = (const int4*)(AIsm + (c % NST) * AI_STAGE);
        __half*     dst = Afp + (c & 1) * AF_STAGE;
#pragma unroll
        for (int q = 0; q < 4; ++q) {
            int idx = q * 256 + tid;
            int rr = idx >> 4, c4 = idx & 15;
            int4 v = src[rr * 17 + c4];
            uint32_t h01 = (v.x ? 0x3C00u : 0u) | (v.y ? 0x3C000000u : 0u);
            uint32_t h23 = (v.z ? 0x3C00u : 0u) | (v.w ? 0x3C000000u : 0u);
            *(uint2*)&dst[rr * 72 + c4 * 4] = make_uint2(h01, h23);
        }
    };

    issue(0); CP_COMMIT();
    issue(1); CP_COMMIT();

    float acc[5][4];
#pragma unroll
    for (int n = 0; n < 5; ++n)
#pragma unroll
        for (int i = 0; i < 4; ++i) acc[n][i] = 0.f;

    CP_WAIT(1);
    convA(0);
    __syncthreads();

    for (int c = 0; c < 64; ++c) {
        if (c + 2 < 64) issue(c + 2);
        CP_COMMIT();
        CP_WAIT(1);

        if (c + 1 < 64) convA(c + 1);

        const uint32_t Ab = A0 + (c & 1) * (AF_STAGE * 2) + aoff;
        const uint32_t Bb = B0 + (c % NST) * (B_STAGE * 2);

#pragma unroll
        for (int ks = 0; ks < 4; ++ks) {
            uint32_t a0, a1, a2, a3;
            ldsm_x4(a0, a1, a2, a3, Ab + ks * 32);
            uint32_t b[10];
            ldsm_x4(b[0], b[1], b[2], b[3], Bb + boffp[0] + ks * 32);
            ldsm_x4(b[4], b[5], b[6], b[7], Bb + boffp[1] + ks * 32);
            if (ng == 0) ldsm_x2(b[8], b[9], Bb + boffs + ks * 32);
            mma16816(acc[0], a0, a1, a2, a3, b[0], b[1]);
            mma16816(acc[1], a0, a1, a2, a3, b[2], b[3]);
            mma16816(acc[2], a0, a1, a2, a3, b[4], b[5]);
            mma16816(acc[3], a0, a1, a2, a3, b[6], b[7]);
            if (ng == 0) mma16816(acc[4], a0, a1, a2, a3, b[8], b[9]);
        }
        __syncthreads();
    }

    // store raw partials (cols: ng0 -> 0..39, ng1 -> 40..71 incl den col 64)
    const int g   = lane >> 2;
    const int r0l = rb + g;
    float* P = d_part + (size_t)half * N_NODES * 80;
    const int rlo = row0 + r0l;
    const int rhi = rlo + 8;
#pragma unroll
    for (int nt = 0; nt < 5; ++nt) {
        if (nt >= cntT) break;
        int gt = baseT + nt;
        int c0 = gt * 8 + 2 * t;
        *(float2*)&P[(size_t)rlo * 80 + c0] = make_float2(acc[nt][0], acc[nt][1]);
        *(float2*)&P[(size_t)rhi * 80 + c0] = make_float2(acc[nt][2], acc[nt][3]);
    }
}

// ---------------------------------------------------------------------------
// K5: combine halves: out = elu((num0+num1)/(den0+den1))
// ---------------------------------------------------------------------------
__global__ void __launch_bounds__(256)
k5_combine(float* __restrict__ out) {
    const int idx = blockIdx.x * 256 + threadIdx.x;    // one float4 of output
    const int row = idx >> 4;
    const int c0  = (idx & 15) * 4;
    const float* P0 = d_part + (size_t)row * 80;
    const float* P1 = d_part + (size_t)N_NODES * 80 + (size_t)row * 80;
    float4 n0 = *(const float4*)&P0[c0];
    float4 n1 = *(const float4*)&P1[c0];
    float den = P0[64] + P1[64];
    float inv = 1.f / den;
    float4 o;
    o.x = elu1((n0.x + n1.x) * inv);
    o.y = elu1((n0.y + n1.y) * inv);
    o.z = elu1((n0.z + n1.z) * inv);
    o.w = elu1((n0.w + n1.w) * inv);
    *(float4*)&out[(size_t)row * OUT_F + c0] = o;
}

// ---------------------------------------------------------------------------
extern "C" void kernel_launch(void* const* d_in, const int* in_sizes, int n_in,
                              void* d_out, int out_size) {
    const float* X    = (const float*)d_in[0];
    const int*   adj  = (const int*)  d_in[1];
    const float* W    = (const float*)d_in[2];
    const float* avec = (const float*)d_in[3];
    float* out = (float*)d_out;

    cudaFuncSetAttribute(k1_mma, cudaFuncAttributeMaxDynamicSharedMemorySize, K1_SMEM);
    cudaFuncSetAttribute(k4_split, cudaFuncAttributeMaxDynamicSharedMemorySize, K4_SMEM);

    k1_mma<<<128, 128, K1_SMEM>>>(X, W, avec);
    k3_build<<<64, 128>>>();
    k4_split<<<256, 256, K4_SMEM>>>(adj);
    k5_combine<<<N_NODES * OUT_F / 1024, 256>>>(out);
}